// round 5
// baseline (speedup 1.0000x reference)
#include <cuda_runtime.h>
#include <cuda_bf16.h>

// GCN 2-layer, minimal-traffic formulation:
//   y[i]   = x[i] * dinv[i]  (5 floats padded to 8 = one 32B L2 sector)
//   z[d]   = sum_edges y[src]          (red.v4 + red.f32, 2 atomics/edge)
//   zt     = z*dinv + x*dinv^2 ; h = relu(zt@W1+b1) ; s = h.W2
//   t[i]   = s[i]*dinv[i]
//   acc[d] = sum_edges t[src]          (1 atomic/edge)
//   out[i] = acc[i]*dinv[i] + s[i]*dinv[i]^2 + b2

#define MAXN 131072
#define IN_DIM 5
#define PAD 8
#define HID 128

__device__ float g_deg[MAXN];
__device__ float g_dinv[MAXN];
__device__ __align__(128) float g_y[MAXN * PAD];
__device__ __align__(128) float g_z[MAXN * PAD];
__device__ float g_t[MAXN];
__device__ float g_acc[MAXN];

__device__ __forceinline__ void red_v4(float* p, float a, float b, float c, float d) {
    asm volatile("red.global.add.v4.f32 [%0], {%1, %2, %3, %4};"
                 :: "l"(p), "f"(a), "f"(b), "f"(c), "f"(d) : "memory");
}

__global__ void k_zero(int n) {
    int i = blockIdx.x * blockDim.x + threadIdx.x;
    if (i >= n) return;
    g_deg[i] = 0.0f;
    g_acc[i] = 0.0f;
    float4 z4 = make_float4(0.f, 0.f, 0.f, 0.f);
    *(float4*)&g_z[i * PAD] = z4;
    *(float4*)&g_z[i * PAD + 4] = z4;
}

// ---- degree: 1 edge/thread (measured-fastest config) ----
__global__ void k_degree(const int* __restrict__ dst, int E) {
    int e = blockIdx.x * blockDim.x + threadIdx.x;
    if (e >= E) return;
    atomicAdd(&g_deg[dst[e]], 1.0f);
}

// ---- dinv + scaled padded features ----
__global__ void k_prep(const float* __restrict__ x, int n) {
    int i = blockIdx.x * blockDim.x + threadIdx.x;
    if (i >= n) return;
    float di = rsqrtf(g_deg[i] + 1.0f);
    g_dinv[i] = di;
    float y0 = x[i * IN_DIM + 0] * di;
    float y1 = x[i * IN_DIM + 1] * di;
    float y2 = x[i * IN_DIM + 2] * di;
    float y3 = x[i * IN_DIM + 3] * di;
    float y4 = x[i * IN_DIM + 4] * di;
    *(float4*)&g_y[i * PAD] = make_float4(y0, y1, y2, y3);
    *(float4*)&g_y[i * PAD + 4] = make_float4(y4, 0.f, 0.f, 0.f);
}

// ---- edge pass 1: z[dst] += y[src], 1 edge/thread ----
__global__ void k_edge_agg1(const int* __restrict__ src, const int* __restrict__ dst, int E) {
    int e = blockIdx.x * blockDim.x + threadIdx.x;
    if (e >= E) return;
    int s = src[e];
    int d = dst[e];
    float4 a = *(const float4*)&g_y[s * PAD];
    float h = g_y[s * PAD + 4];
    red_v4(&g_z[d * PAD], a.x, a.y, a.z, a.w);
    atomicAdd(&g_z[d * PAD + 4], h);
}

// ---- per-node MLP, split-K: 4 threads per node, 32 hidden units each ----
__global__ void k_node(const float* __restrict__ x,
                       const float* __restrict__ W1, const float* __restrict__ b1,
                       const float* __restrict__ W2, const float* __restrict__ b2,
                       float* __restrict__ out, int n) {
    __shared__ float sW1[IN_DIM * HID];
    __shared__ float sb1[HID];
    __shared__ float sW2[HID];
    for (int i = threadIdx.x; i < IN_DIM * HID; i += blockDim.x) sW1[i] = W1[i];
    if (threadIdx.x < HID) {
        sb1[threadIdx.x] = b1[threadIdx.x];
        sW2[threadIdx.x] = W2[threadIdx.x];
    }
    __syncthreads();

    int gt = blockIdx.x * blockDim.x + threadIdx.x;
    int i  = gt >> 2;          // node index
    int kk = gt & 3;           // k-chunk 0..3
    if (i >= n) return;

    float di = g_dinv[i];
    float d2 = di * di;
    float zt[IN_DIM];
#pragma unroll
    for (int j = 0; j < IN_DIM; j++) {
        zt[j] = g_z[i * PAD + j] * di + x[i * IN_DIM + j] * d2;
    }

    int k0 = kk * (HID / 4);
    float s0 = 0.0f, s1 = 0.0f;
#pragma unroll
    for (int kq = 0; kq < HID / 8; kq++) {
        int ka = k0 + kq * 2;
        int kb = ka + 1;
        float a = sb1[ka], b = sb1[kb];
#pragma unroll
        for (int j = 0; j < IN_DIM; j++) {
            a = fmaf(zt[j], sW1[j * HID + ka], a);
            b = fmaf(zt[j], sW1[j * HID + kb], b);
        }
        s0 = fmaf(fmaxf(a, 0.0f), sW2[ka], s0);
        s1 = fmaf(fmaxf(b, 0.0f), sW2[kb], s1);
    }
    float s = s0 + s1;
    // reduce across the 4-thread group (lanes 4q..4q+3)
    s += __shfl_xor_sync(0xFFFFFFFFu, s, 1);
    s += __shfl_xor_sync(0xFFFFFFFFu, s, 2);
    if (kk == 0) {
        g_t[i] = s * di;
        out[i] = s * d2 + b2[0];
    }
}

// ---- edge pass 2: acc[dst] += t[src], 1 edge/thread ----
__global__ void k_edge_agg2(const int* __restrict__ src, const int* __restrict__ dst, int E) {
    int e = blockIdx.x * blockDim.x + threadIdx.x;
    if (e >= E) return;
    atomicAdd(&g_acc[dst[e]], g_t[src[e]]);
}

__global__ void k_final(float* __restrict__ out, int n) {
    int i = blockIdx.x * blockDim.x + threadIdx.x;
    if (i >= n) return;
    out[i] += g_acc[i] * g_dinv[i];
}

extern "C" void kernel_launch(void* const* d_in, const int* in_sizes, int n_in,
                              void* d_out, int out_size) {
    const float* x  = (const float*)d_in[0];
    const int* ei   = (const int*)d_in[1];   // [2, E]: src row then dst row
    const float* W1 = (const float*)d_in[2];
    const float* b1 = (const float*)d_in[3];
    const float* W2 = (const float*)d_in[4];
    const float* b2 = (const float*)d_in[5];
    float* out = (float*)d_out;

    int n = in_sizes[0] / IN_DIM;
    int E = in_sizes[1] / 2;
    const int* src = ei;
    const int* dst = ei + E;

    const int TB = 256;
    int gb_n  = (n + TB - 1) / TB;
    int gb_n4 = (n * 4 + TB - 1) / TB;
    int gb_e  = (E + TB - 1) / TB;

    k_zero<<<gb_n, TB>>>(n);
    k_degree<<<gb_e, TB>>>(dst, E);
    k_prep<<<gb_n, TB>>>(x, n);
    k_edge_agg1<<<gb_e, TB>>>(src, dst, E);
    k_node<<<gb_n4, TB>>>(x, W1, b1, W2, b2, out, n);
    k_edge_agg2<<<gb_e, TB>>>(src, dst, E);
    k_final<<<gb_n, TB>>>(out, n);
}

// round 6
// speedup vs baseline: 1.3630x; 1.3630x over previous
#include <cuda_runtime.h>
#include <cuda_bf16.h>

// GCN 2-layer, minimal-traffic formulation:
//   y[i]   = x[i] * dinv[i]  (5 floats padded to 8 = one 32B L2 sector)
//   z[d]   = sum_edges y[src]          (red.v4 + red.f32)
//   zt     = z*dinv + x*dinv^2 ; h = relu(zt@W1+b1) ; s = h.W2
//   t[i]   = s[i]*dinv[i]
//   acc[d] = sum_edges t[src]          (1 atomic/edge)
//   out[i] = acc[i]*dinv[i] + s[i]*dinv[i]^2 + b2

#define MAXN 131072
#define IN_DIM 5
#define PAD 8
#define HID 128

__device__ float g_deg[MAXN];
__device__ float g_dinv[MAXN];
__device__ __align__(128) float g_y[MAXN * PAD];
__device__ __align__(128) float g_z[MAXN * PAD];
__device__ float g_t[MAXN];
__device__ float g_acc[MAXN];

__device__ __forceinline__ void red_v4(float* p, float a, float b, float c, float d) {
    asm volatile("red.global.add.v4.f32 [%0], {%1, %2, %3, %4};"
                 :: "l"(p), "f"(a), "f"(b), "f"(c), "f"(d) : "memory");
}

// ---- degree: 1 edge/thread (measured-fastest config) ----
__global__ void k_degree(const int* __restrict__ dst, int E) {
    int e = blockIdx.x * blockDim.x + threadIdx.x;
    if (e >= E) return;
    atomicAdd(&g_deg[dst[e]], 1.0f);
}

// ---- dinv + scaled padded features ----
__global__ void k_prep(const float* __restrict__ x, int n) {
    int i = blockIdx.x * blockDim.x + threadIdx.x;
    if (i >= n) return;
    float di = rsqrtf(g_deg[i] + 1.0f);
    g_dinv[i] = di;
    float y0 = x[i * IN_DIM + 0] * di;
    float y1 = x[i * IN_DIM + 1] * di;
    float y2 = x[i * IN_DIM + 2] * di;
    float y3 = x[i * IN_DIM + 3] * di;
    float y4 = x[i * IN_DIM + 4] * di;
    *(float4*)&g_y[i * PAD] = make_float4(y0, y1, y2, y3);
    *(float4*)&g_y[i * PAD + 4] = make_float4(y4, 0.f, 0.f, 0.f);
}

// ---- edge pass 1: z[dst] += y[src], 1 edge/thread ----
__global__ void k_edge_agg1(const int* __restrict__ src, const int* __restrict__ dst, int E) {
    int e = blockIdx.x * blockDim.x + threadIdx.x;
    if (e >= E) return;
    int s = src[e];
    int d = dst[e];
    float4 a = *(const float4*)&g_y[s * PAD];
    float h = g_y[s * PAD + 4];
    red_v4(&g_z[d * PAD], a.x, a.y, a.z, a.w);
    atomicAdd(&g_z[d * PAD + 4], h);
}

// ---- per-node MLP, split-K: 4 threads/node, interleaved k = kk + 4*kq ----
// Shared weights transposed+packed: row k = [w0,w1,w2,w3 | w4,b1,W2,pad]
// -> 2x LDS.128 per hidden unit, conflict-free (banks 0/8/16/24 per group).
__global__ void k_node(const float* __restrict__ x,
                       const float* __restrict__ W1, const float* __restrict__ b1,
                       const float* __restrict__ W2, const float* __restrict__ b2,
                       float* __restrict__ out, int n) {
    __shared__ __align__(16) float sWt[HID * 8];
    // pack: 8 floats per k
    for (int k = threadIdx.x; k < HID; k += blockDim.x) {
        sWt[k * 8 + 0] = W1[0 * HID + k];
        sWt[k * 8 + 1] = W1[1 * HID + k];
        sWt[k * 8 + 2] = W1[2 * HID + k];
        sWt[k * 8 + 3] = W1[3 * HID + k];
        sWt[k * 8 + 4] = W1[4 * HID + k];
        sWt[k * 8 + 5] = b1[k];
        sWt[k * 8 + 6] = W2[k];
        sWt[k * 8 + 7] = 0.0f;
    }
    __syncthreads();

    int gt = blockIdx.x * blockDim.x + threadIdx.x;
    int i  = gt >> 2;          // node index
    int kk = gt & 3;           // k-chunk lane 0..3
    bool valid = (i < n);
    if (i >= n) i = n - 1;     // clamp: keep all lanes active for shfl

    float di = g_dinv[i];
    float d2 = di * di;
    float4 z4 = *(const float4*)&g_z[i * PAD];
    float z5  = g_z[i * PAD + 4];
    float zt0 = z4.x * di + x[i * IN_DIM + 0] * d2;
    float zt1 = z4.y * di + x[i * IN_DIM + 1] * d2;
    float zt2 = z4.z * di + x[i * IN_DIM + 2] * d2;
    float zt3 = z4.w * di + x[i * IN_DIM + 3] * d2;
    float zt4 = z5  * di + x[i * IN_DIM + 4] * d2;

    float s0 = 0.0f, s1 = 0.0f;
#pragma unroll
    for (int kq = 0; kq < HID / 8; kq++) {
        // two k's per iter for ILP: k = kk + 4*(2kq) and kk + 4*(2kq+1)
        int ka = kk + 8 * kq;
        int kb = ka + 4;
        float4 wa0 = *(const float4*)&sWt[ka * 8];
        float4 wa1 = *(const float4*)&sWt[ka * 8 + 4];
        float4 wb0 = *(const float4*)&sWt[kb * 8];
        float4 wb1 = *(const float4*)&sWt[kb * 8 + 4];
        float a = wa1.y;  // b1
        a = fmaf(zt0, wa0.x, a);
        a = fmaf(zt1, wa0.y, a);
        a = fmaf(zt2, wa0.z, a);
        a = fmaf(zt3, wa0.w, a);
        a = fmaf(zt4, wa1.x, a);
        float b = wb1.y;
        b = fmaf(zt0, wb0.x, b);
        b = fmaf(zt1, wb0.y, b);
        b = fmaf(zt2, wb0.z, b);
        b = fmaf(zt3, wb0.w, b);
        b = fmaf(zt4, wb1.x, b);
        s0 = fmaf(fmaxf(a, 0.0f), wa1.z, s0);
        s1 = fmaf(fmaxf(b, 0.0f), wb1.z, s1);
    }
    float s = s0 + s1;
    s += __shfl_xor_sync(0xFFFFFFFFu, s, 1);
    s += __shfl_xor_sync(0xFFFFFFFFu, s, 2);
    if (valid && kk == 0) {
        g_t[i] = s * di;
        out[i] = s * d2 + b2[0];
    }
}

// ---- edge pass 2: acc[dst] += t[src], 1 edge/thread ----
__global__ void k_edge_agg2(const int* __restrict__ src, const int* __restrict__ dst, int E) {
    int e = blockIdx.x * blockDim.x + threadIdx.x;
    if (e >= E) return;
    atomicAdd(&g_acc[dst[e]], g_t[src[e]]);
}

__global__ void k_final(float* __restrict__ out, int n) {
    int i = blockIdx.x * blockDim.x + threadIdx.x;
    if (i >= n) return;
    out[i] += g_acc[i] * g_dinv[i];
}

extern "C" void kernel_launch(void* const* d_in, const int* in_sizes, int n_in,
                              void* d_out, int out_size) {
    const float* x  = (const float*)d_in[0];
    const int* ei   = (const int*)d_in[1];   // [2, E]: src row then dst row
    const float* W1 = (const float*)d_in[2];
    const float* b1 = (const float*)d_in[3];
    const float* W2 = (const float*)d_in[4];
    const float* b2 = (const float*)d_in[5];
    float* out = (float*)d_out;

    int n = in_sizes[0] / IN_DIM;
    int E = in_sizes[1] / 2;
    const int* src = ei;
    const int* dst = ei + E;

    // zero scratch via memset nodes (graph-capturable, no alloc)
    void *p_deg, *p_z, *p_acc;
    cudaGetSymbolAddress(&p_deg, g_deg);
    cudaGetSymbolAddress(&p_z, g_z);
    cudaGetSymbolAddress(&p_acc, g_acc);
    cudaMemsetAsync(p_deg, 0, (size_t)n * sizeof(float));
    cudaMemsetAsync(p_z, 0, (size_t)n * PAD * sizeof(float));
    cudaMemsetAsync(p_acc, 0, (size_t)n * sizeof(float));

    const int TB = 256;
    int gb_n  = (n + TB - 1) / TB;
    int gb_n4 = (n * 4 + TB - 1) / TB;
    int gb_e  = (E + TB - 1) / TB;

    k_degree<<<gb_e, TB>>>(dst, E);
    k_prep<<<gb_n, TB>>>(x, n);
    k_edge_agg1<<<gb_e, TB>>>(src, dst, E);
    k_node<<<gb_n4, TB>>>(x, W1, b1, W2, b2, out, n);
    k_edge_agg2<<<gb_e, TB>>>(src, dst, E);
    k_final<<<gb_n, TB>>>(out, n);
}

// round 7
// speedup vs baseline: 1.4444x; 1.0597x over previous
#include <cuda_runtime.h>
#include <cuda_bf16.h>

// GCN 2-layer, minimal-traffic formulation:
//   y[i]   = x[i] * dinv[i]  (5 floats padded to 8 = one 32B L2 sector)
//   z[d]   = sum_edges y[src]          (red.v4 + red.f32)
//   zt     = z*dinv + x*dinv^2 ; h = relu(zt@W1+b1) ; s = h.W2
//   t[i]   = s[i]*dinv[i]
//   acc[d] = sum_edges t[src]          (1 atomic/edge)
//   out[i] = acc[i]*dinv[i] + s[i]*dinv[i]^2 + b2

#define MAXN 131072
#define IN_DIM 5
#define PAD 8
#define HID 128

__device__ float g_deg[MAXN];
__device__ float g_dinv[MAXN];
__device__ __align__(128) float g_y[MAXN * PAD];
__device__ __align__(128) float g_z[MAXN * PAD];
__device__ float g_t[MAXN];
__device__ float g_acc[MAXN];

__device__ __forceinline__ void red_v4(float* p, float a, float b, float c, float d) {
    asm volatile("red.global.add.v4.f32 [%0], {%1, %2, %3, %4};"
                 :: "l"(p), "f"(a), "f"(b), "f"(c), "f"(d) : "memory");
}

// ---- degree: 1 edge/thread (measured-fastest config) ----
__global__ void k_degree(const int* __restrict__ dst, int E) {
    int e = blockIdx.x * blockDim.x + threadIdx.x;
    if (e >= E) return;
    atomicAdd(&g_deg[dst[e]], 1.0f);
}

// ---- dinv + scaled padded features ----
__global__ void k_prep(const float* __restrict__ x, int n) {
    int i = blockIdx.x * blockDim.x + threadIdx.x;
    if (i >= n) return;
    float di = rsqrtf(g_deg[i] + 1.0f);
    g_dinv[i] = di;
    float y0 = x[i * IN_DIM + 0] * di;
    float y1 = x[i * IN_DIM + 1] * di;
    float y2 = x[i * IN_DIM + 2] * di;
    float y3 = x[i * IN_DIM + 3] * di;
    float y4 = x[i * IN_DIM + 4] * di;
    *(float4*)&g_y[i * PAD] = make_float4(y0, y1, y2, y3);
    *(float4*)&g_y[i * PAD + 4] = make_float4(y4, 0.f, 0.f, 0.f);
}

// ---- edge pass 1: z[dst] += y[src], 1 edge/thread ----
__global__ void k_edge_agg1(const int* __restrict__ src, const int* __restrict__ dst, int E) {
    int e = blockIdx.x * blockDim.x + threadIdx.x;
    if (e >= E) return;
    int s = src[e];
    int d = dst[e];
    float4 a = *(const float4*)&g_y[s * PAD];
    float h = g_y[s * PAD + 4];
    red_v4(&g_z[d * PAD], a.x, a.y, a.z, a.w);
    atomicAdd(&g_z[d * PAD + 4], h);
}

// ---- per-node MLP: 2 threads/node, adjacent-k interleave (k = kk + 2*kq) ----
// Packed weight rows (8 floats): [w0..w3 | w4, b1, W2, pad] -> 2x LDS.128 per k.
// Lane pair reads rows 32B apart (banks 0-7 / 8-15): conflict-free, broadcast
// across the 16 node-pairs in a warp. 4 independent accumulator chains.
__global__ void k_node(const float* __restrict__ x,
                       const float* __restrict__ W1, const float* __restrict__ b1,
                       const float* __restrict__ W2, const float* __restrict__ b2,
                       float* __restrict__ out, int n) {
    __shared__ __align__(16) float sWt[HID * 8];
    for (int k = threadIdx.x; k < HID; k += blockDim.x) {
        sWt[k * 8 + 0] = W1[0 * HID + k];
        sWt[k * 8 + 1] = W1[1 * HID + k];
        sWt[k * 8 + 2] = W1[2 * HID + k];
        sWt[k * 8 + 3] = W1[3 * HID + k];
        sWt[k * 8 + 4] = W1[4 * HID + k];
        sWt[k * 8 + 5] = b1[k];
        sWt[k * 8 + 6] = W2[k];
        sWt[k * 8 + 7] = 0.0f;
    }
    __syncthreads();

    int gt = blockIdx.x * blockDim.x + threadIdx.x;
    int i  = gt >> 1;          // node index
    int kk = gt & 1;           // k parity
    bool valid = (i < n);
    if (!valid) i = n - 1;     // clamp: keep all lanes active for shfl

    float di = g_dinv[i];
    float d2 = di * di;
    float4 z4 = *(const float4*)&g_z[i * PAD];
    float z5  = g_z[i * PAD + 4];
    float zt0 = z4.x * di + x[i * IN_DIM + 0] * d2;
    float zt1 = z4.y * di + x[i * IN_DIM + 1] * d2;
    float zt2 = z4.z * di + x[i * IN_DIM + 2] * d2;
    float zt3 = z4.w * di + x[i * IN_DIM + 3] * d2;
    float zt4 = z5  * di + x[i * IN_DIM + 4] * d2;

    float s0 = 0.0f, s1 = 0.0f, s2 = 0.0f, s3 = 0.0f;
#pragma unroll
    for (int q = 0; q < HID / 8; q++) {
        int k0 = kk + 8 * q;   // 4 k's this iter: k0, k0+2, k0+4, k0+6
#pragma unroll
        for (int u = 0; u < 4; u++) {
            int k = k0 + 2 * u;
            float4 w0 = *(const float4*)&sWt[k * 8];
            float4 w1 = *(const float4*)&sWt[k * 8 + 4];
            float a = w1.y;                 // b1
            a = fmaf(zt0, w0.x, a);
            a = fmaf(zt1, w0.y, a);
            a = fmaf(zt2, w0.z, a);
            a = fmaf(zt3, w0.w, a);
            a = fmaf(zt4, w1.x, a);
            a = fmaxf(a, 0.0f);
            if (u == 0)      s0 = fmaf(a, w1.z, s0);
            else if (u == 1) s1 = fmaf(a, w1.z, s1);
            else if (u == 2) s2 = fmaf(a, w1.z, s2);
            else             s3 = fmaf(a, w1.z, s3);
        }
    }
    float s = (s0 + s1) + (s2 + s3);
    s += __shfl_xor_sync(0xFFFFFFFFu, s, 1);
    if (valid && kk == 0) {
        g_t[i] = s * di;
        out[i] = s * d2 + b2[0];
    }
}

// ---- edge pass 2: acc[dst] += t[src], 1 edge/thread ----
__global__ void k_edge_agg2(const int* __restrict__ src, const int* __restrict__ dst, int E) {
    int e = blockIdx.x * blockDim.x + threadIdx.x;
    if (e >= E) return;
    atomicAdd(&g_acc[dst[e]], g_t[src[e]]);
}

__global__ void k_final(float* __restrict__ out, int n) {
    int i = blockIdx.x * blockDim.x + threadIdx.x;
    if (i >= n) return;
    out[i] += g_acc[i] * g_dinv[i];
}

extern "C" void kernel_launch(void* const* d_in, const int* in_sizes, int n_in,
                              void* d_out, int out_size) {
    const float* x  = (const float*)d_in[0];
    const int* ei   = (const int*)d_in[1];   // [2, E]: src row then dst row
    const float* W1 = (const float*)d_in[2];
    const float* b1 = (const float*)d_in[3];
    const float* W2 = (const float*)d_in[4];
    const float* b2 = (const float*)d_in[5];
    float* out = (float*)d_out;

    int n = in_sizes[0] / IN_DIM;
    int E = in_sizes[1] / 2;
    const int* src = ei;
    const int* dst = ei + E;

    // zero scratch via memset nodes (graph-capturable, no alloc)
    void *p_deg, *p_z, *p_acc;
    cudaGetSymbolAddress(&p_deg, g_deg);
    cudaGetSymbolAddress(&p_z, g_z);
    cudaGetSymbolAddress(&p_acc, g_acc);
    cudaMemsetAsync(p_deg, 0, (size_t)n * sizeof(float));
    cudaMemsetAsync(p_z, 0, (size_t)n * PAD * sizeof(float));
    cudaMemsetAsync(p_acc, 0, (size_t)n * sizeof(float));

    const int TB = 256;
    int gb_n  = (n + TB - 1) / TB;
    int gb_n2 = (n * 2 + TB - 1) / TB;
    int gb_e  = (E + TB - 1) / TB;

    k_degree<<<gb_e, TB>>>(dst, E);
    k_prep<<<gb_n, TB>>>(x, n);
    k_edge_agg1<<<gb_e, TB>>>(src, dst, E);
    k_node<<<gb_n2, TB>>>(x, W1, b1, W2, b2, out, n);
    k_edge_agg2<<<gb_e, TB>>>(src, dst, E);
    k_final<<<gb_n, TB>>>(out, n);
}

// round 8
// speedup vs baseline: 1.4868x; 1.0293x over previous
#include <cuda_runtime.h>
#include <cuda_bf16.h>

// GCN 2-layer, minimal-traffic formulation:
//   y[i]   = x[i] * dinv[i]  (5 floats padded to 8 = one 32B L2 sector)
//   z[d]   = sum_edges y[src]          (red.v4 + red.f32)
//   zt     = z*dinv + x*dinv^2 ; h = relu(zt@W1+b1) ; s = h.W2
//   t[i]   = s[i]*dinv[i]
//   acc[d] = sum_edges t[src]          (1 atomic/edge)
//   out[i] = acc[i]*dinv[i] + s[i]*dinv[i]^2 + b2

#define MAXN 131072
#define IN_DIM 5
#define PAD 8
#define HID 128

__device__ float g_deg[MAXN];
__device__ float g_dinv[MAXN];
__device__ __align__(128) float g_y[MAXN * PAD];
__device__ __align__(128) float g_z[MAXN * PAD];
__device__ float g_t[MAXN];
__device__ float g_acc[MAXN];

// weights live in constant memory: warp-uniform reads go down the uniform
// (LDCU) path, freeing LSU/L1 entirely in k_node.
__constant__ float cW1[IN_DIM * HID];   // [j][k] layout: pairs (k, k+1) are 8B-aligned
__constant__ float cb1[HID];
__constant__ float cW2[HID];
__constant__ float cb2[1];

__device__ __forceinline__ void red_v4(float* p, float a, float b, float c, float d) {
    asm volatile("red.global.add.v4.f32 [%0], {%1, %2, %3, %4};"
                 :: "l"(p), "f"(a), "f"(b), "f"(c), "f"(d) : "memory");
}

__device__ __forceinline__ unsigned long long fma2(unsigned long long a,
                                                   unsigned long long b,
                                                   unsigned long long c) {
    unsigned long long d;
    asm("fma.rn.f32x2 %0, %1, %2, %3;" : "=l"(d) : "l"(a), "l"(b), "l"(c));
    return d;
}
__device__ __forceinline__ unsigned long long pack2(float lo, float hi) {
    unsigned long long d;
    asm("mov.b64 %0, {%1, %2};" : "=l"(d) : "f"(lo), "f"(hi));
    return d;
}
__device__ __forceinline__ void unpack2(unsigned long long v, float& lo, float& hi) {
    asm("mov.b64 {%0, %1}, %2;" : "=f"(lo), "=f"(hi) : "l"(v));
}

__global__ void k_zero(int n) {
    int i = blockIdx.x * blockDim.x + threadIdx.x;
    if (i >= n) return;
    g_deg[i] = 0.0f;
    g_acc[i] = 0.0f;
    float4 z4 = make_float4(0.f, 0.f, 0.f, 0.f);
    *(float4*)&g_z[i * PAD] = z4;
    *(float4*)&g_z[i * PAD + 4] = z4;
}

// ---- degree: 1 edge/thread (measured-fastest config) ----
__global__ void k_degree(const int* __restrict__ dst, int E) {
    int e = blockIdx.x * blockDim.x + threadIdx.x;
    if (e >= E) return;
    atomicAdd(&g_deg[dst[e]], 1.0f);
}

// ---- dinv + scaled padded features ----
__global__ void k_prep(const float* __restrict__ x, int n) {
    int i = blockIdx.x * blockDim.x + threadIdx.x;
    if (i >= n) return;
    float di = rsqrtf(g_deg[i] + 1.0f);
    g_dinv[i] = di;
    float y0 = x[i * IN_DIM + 0] * di;
    float y1 = x[i * IN_DIM + 1] * di;
    float y2 = x[i * IN_DIM + 2] * di;
    float y3 = x[i * IN_DIM + 3] * di;
    float y4 = x[i * IN_DIM + 4] * di;
    *(float4*)&g_y[i * PAD] = make_float4(y0, y1, y2, y3);
    *(float4*)&g_y[i * PAD + 4] = make_float4(y4, 0.f, 0.f, 0.f);
}

// ---- edge pass 1: z[dst] += y[src], 1 edge/thread ----
__global__ void k_edge_agg1(const int* __restrict__ src, const int* __restrict__ dst, int E) {
    int e = blockIdx.x * blockDim.x + threadIdx.x;
    if (e >= E) return;
    int s = src[e];
    int d = dst[e];
    float4 a = *(const float4*)&g_y[s * PAD];
    float h = g_y[s * PAD + 4];
    red_v4(&g_z[d * PAD], a.x, a.y, a.z, a.w);
    atomicAdd(&g_z[d * PAD + 4], h);
}

// ---- per-node MLP: 1 thread/node, f32x2 packed FMA, constant-memory weights.
// Per pair of hidden units: 5 FFMA2 + unpack + 2 FMAX + 2 FFMA; no LDS/LDG for
// weights (uniform LDCU). 4 independent accumulator chains.
__global__ void k_node(const float* __restrict__ x, float* __restrict__ out, int n) {
    int i = blockIdx.x * blockDim.x + threadIdx.x;
    if (i >= n) return;

    float di = g_dinv[i];
    float d2 = di * di;
    float4 z4 = *(const float4*)&g_z[i * PAD];
    float z5  = g_z[i * PAD + 4];
    float zt0 = z4.x * di + x[i * IN_DIM + 0] * d2;
    float zt1 = z4.y * di + x[i * IN_DIM + 1] * d2;
    float zt2 = z4.z * di + x[i * IN_DIM + 2] * d2;
    float zt3 = z4.w * di + x[i * IN_DIM + 3] * d2;
    float zt4 = z5  * di + x[i * IN_DIM + 4] * d2;

    unsigned long long zp0 = pack2(zt0, zt0);
    unsigned long long zp1 = pack2(zt1, zt1);
    unsigned long long zp2 = pack2(zt2, zt2);
    unsigned long long zp3 = pack2(zt3, zt3);
    unsigned long long zp4 = pack2(zt4, zt4);

    float s0 = 0.0f, s1 = 0.0f, s2 = 0.0f, s3 = 0.0f;
#pragma unroll
    for (int k = 0; k < HID; k += 4) {
        // pair A: units k, k+1
        unsigned long long a = *(const unsigned long long*)&cb1[k];
        a = fma2(zp0, *(const unsigned long long*)&cW1[0 * HID + k], a);
        a = fma2(zp1, *(const unsigned long long*)&cW1[1 * HID + k], a);
        a = fma2(zp2, *(const unsigned long long*)&cW1[2 * HID + k], a);
        a = fma2(zp3, *(const unsigned long long*)&cW1[3 * HID + k], a);
        a = fma2(zp4, *(const unsigned long long*)&cW1[4 * HID + k], a);
        // pair B: units k+2, k+3
        unsigned long long b = *(const unsigned long long*)&cb1[k + 2];
        b = fma2(zp0, *(const unsigned long long*)&cW1[0 * HID + k + 2], b);
        b = fma2(zp1, *(const unsigned long long*)&cW1[1 * HID + k + 2], b);
        b = fma2(zp2, *(const unsigned long long*)&cW1[2 * HID + k + 2], b);
        b = fma2(zp3, *(const unsigned long long*)&cW1[3 * HID + k + 2], b);
        b = fma2(zp4, *(const unsigned long long*)&cW1[4 * HID + k + 2], b);
        float a0, a1, b0, b1v;
        unpack2(a, a0, a1);
        unpack2(b, b0, b1v);
        s0 = fmaf(fmaxf(a0, 0.0f), cW2[k + 0], s0);
        s1 = fmaf(fmaxf(a1, 0.0f), cW2[k + 1], s1);
        s2 = fmaf(fmaxf(b0, 0.0f), cW2[k + 2], s2);
        s3 = fmaf(fmaxf(b1v, 0.0f), cW2[k + 3], s3);
    }
    float s = (s0 + s1) + (s2 + s3);
    g_t[i] = s * di;
    out[i] = s * d2 + cb2[0];
}

// ---- edge pass 2: acc[dst] += t[src], 1 edge/thread ----
__global__ void k_edge_agg2(const int* __restrict__ src, const int* __restrict__ dst, int E) {
    int e = blockIdx.x * blockDim.x + threadIdx.x;
    if (e >= E) return;
    atomicAdd(&g_acc[dst[e]], g_t[src[e]]);
}

__global__ void k_final(float* __restrict__ out, int n) {
    int i = blockIdx.x * blockDim.x + threadIdx.x;
    if (i >= n) return;
    out[i] += g_acc[i] * g_dinv[i];
}

extern "C" void kernel_launch(void* const* d_in, const int* in_sizes, int n_in,
                              void* d_out, int out_size) {
    const float* x  = (const float*)d_in[0];
    const int* ei   = (const int*)d_in[1];   // [2, E]: src row then dst row
    const float* W1 = (const float*)d_in[2];
    const float* b1 = (const float*)d_in[3];
    const float* W2 = (const float*)d_in[4];
    const float* b2 = (const float*)d_in[5];
    float* out = (float*)d_out;

    int n = in_sizes[0] / IN_DIM;
    int E = in_sizes[1] / 2;
    const int* src = ei;
    const int* dst = ei + E;

    // weights -> constant memory (D2D copies, graph-capturable)
    cudaMemcpyToSymbolAsync(cW1, W1, IN_DIM * HID * sizeof(float), 0, cudaMemcpyDeviceToDevice);
    cudaMemcpyToSymbolAsync(cb1, b1, HID * sizeof(float), 0, cudaMemcpyDeviceToDevice);
    cudaMemcpyToSymbolAsync(cW2, W2, HID * sizeof(float), 0, cudaMemcpyDeviceToDevice);
    cudaMemcpyToSymbolAsync(cb2, b2, sizeof(float), 0, cudaMemcpyDeviceToDevice);

    const int TB = 256;
    int gb_n = (n + TB - 1) / TB;
    int gb_e = (E + TB - 1) / TB;

    k_zero<<<gb_n, TB>>>(n);
    k_degree<<<gb_e, TB>>>(dst, E);
    k_prep<<<gb_n, TB>>>(x, n);
    k_edge_agg1<<<gb_e, TB>>>(src, dst, E);
    k_node<<<gb_n, TB>>>(x, out, n);
    k_edge_agg2<<<gb_e, TB>>>(src, dst, E);
    k_final<<<gb_n, TB>>>(out, n);
}